// round 4
// baseline (speedup 1.0000x reference)
#include <cuda_runtime.h>
#include <cstdint>

// ---------------------------------------------------------------------------
// GlobalFusion: sparse->dense scatter fusion, DIM=96, C=24.
// Outputs (f32, concatenated in tuple order):
//   updated_mask   [96^3]            off 0
//   current_volume [96^3 * 24]       off 884736
//   global_volume  [96^3 * 24]       off 22118400
//   target_volume  [96^3]            off 43352064
//   valid          [300000]          off 44236800
//   valid_target   [200000]          off 44536800
//   near_mask      [300000]          off 44736800
// Strategy: big volumes zero-filled by cudaMemsetAsync (no deps, starts at
// t=0) on stream 0 while the winner-index chain runs concurrently on
// cudaStreamPerThread; winner rows then scattered on top (graph fork/join).
// ---------------------------------------------------------------------------

#define DIMV   96
#define NCELLS (96 * 96 * 96)   // 884736
#define NC4    6                // 24 floats = 6 float4
#define N_CUR  150000
#define N_GLB  300000
#define N_TGT  100000
#define N_GTGT 200000

#define OFF_UPD 0
#define OFF_CV  884736
#define OFF_GV  22118400
#define OFF_TV  43352064
#define OFF_VAL 44236800
#define OFF_VT  44536800
#define OFF_NR  44736800

#define VOL_BYTES (size_t)(NCELLS * 24 * 4)   // 84,934,656 per feature volume

// Scratch (static device globals; no allocation allowed)
__device__ int           g_cur_win[NCELLS];
__device__ int           g_glb_win[NCELLS];
__device__ int           g_tgt_win[NCELLS];
__device__ unsigned char g_valid_vol[NCELLS];
__device__ unsigned char g_occ[NCELLS];

// --------------------------------------------------------------------------
__global__ void k_init()
{
    int i = blockIdx.x * blockDim.x + threadIdx.x;
    if (i < NCELLS) {
        g_cur_win[i]   = -1;
        g_glb_win[i]   = -1;
        g_tgt_win[i]   = -1;
        g_valid_vol[i] = 0;
        g_occ[i]       = 0;
    }
}

// current-fragment scatter: visibility/occupancy flags + value winner
// (JAX sequential scatter semantics: last duplicate row wins -> atomicMax(i))
__global__ void k_cur(const int* __restrict__ cc,
                      const int* __restrict__ grid_mask,
                      const int* __restrict__ occupancy)
{
    int i = blockIdx.x * blockDim.x + threadIdx.x;
    if (i >= N_CUR) return;
    int x = cc[3 * i + 0];
    int y = cc[3 * i + 1];
    int z = cc[3 * i + 2];
    int cell = (x * DIMV + y) * DIMV + z;
    if (grid_mask[i]) g_valid_vol[cell] = 1;
    if (occupancy[i]) g_occ[cell] = 1;
    atomicMax(&g_cur_win[cell], i);
}

// target scatter (fused): rows [0,N_GTGT) global target (priority i, first);
// rows [N_GTGT, N_GTGT+N_TGT) current target (priority N_GTGT+j, always wins)
__global__ void k_tgt(const int* __restrict__ gct,
                      const int* __restrict__ ct,
                      const int* __restrict__ org,
                      float* __restrict__ out_vt)
{
    int i = blockIdx.x * blockDim.x + threadIdx.x;
    if (i >= N_GTGT + N_TGT) return;

    if (i < N_GTGT) {
        int ox = __ldg(&org[0]), oy = __ldg(&org[1]), oz = __ldg(&org[2]);
        int x = gct[3 * i + 0] - ox;
        int y = gct[3 * i + 1] - oy;
        int z = gct[3 * i + 2] - oz;
        bool inb = ((unsigned)x < DIMV) && ((unsigned)y < DIMV) && ((unsigned)z < DIMV);
        out_vt[i] = inb ? 1.0f : 0.0f;
        if (inb) atomicMax(&g_tgt_win[(x * DIMV + y) * DIMV + z], i);
    } else {
        int j = i - N_GTGT;
        int x = ct[3 * j + 0];
        int y = ct[3 * j + 1];
        int z = ct[3 * j + 2];
        atomicMax(&g_tgt_win[(x * DIMV + y) * DIMV + z], N_GTGT + j);
    }
}

// global-fragment rows: bounds + visibility gather, valid/near, glb winner
__global__ void k_glb(const int* __restrict__ gc,
                      const int* __restrict__ org,
                      float* __restrict__ out_valid,
                      float* __restrict__ out_near)
{
    int i = blockIdx.x * blockDim.x + threadIdx.x;
    if (i >= N_GLB) return;
    int ox = __ldg(&org[0]), oy = __ldg(&org[1]), oz = __ldg(&org[2]);
    int x = gc[3 * i + 0] - ox;
    int y = gc[3 * i + 1] - oy;
    int z = gc[3 * i + 2] - oz;
    bool inb = ((unsigned)x < DIMV) && ((unsigned)y < DIMV) && ((unsigned)z < DIMV);
    bool valid = false;
    if (inb) {
        int cell = (x * DIMV + y) * DIMV + z;
        valid = (g_valid_vol[cell] != 0);
        if (valid) atomicMax(&g_glb_win[cell], i);
    }
    out_valid[i] = valid ? 1.0f : 0.0f;
    out_near[i]  = (inb && !valid) ? 1.0f : 0.0f;
}

// updated_mask + target_volume, one thread per cell, fully coalesced
__global__ void k_upd_tv(const float* __restrict__ g_tsdf,   // [N_GTGT]
                         const float* __restrict__ c_tsdf,   // [N_TGT]
                         float* __restrict__ out)
{
    int cell = blockIdx.x * blockDim.x + threadIdx.x;
    if (cell >= NCELLS) return;
    out[OFF_UPD + cell] = (g_glb_win[cell] >= 0 || g_occ[cell]) ? 1.0f : 0.0f;
    int wt = g_tgt_win[cell];
    float tv = 1.0f;
    if (wt >= 0)
        tv = (wt < N_GTGT) ? __ldg(&g_tsdf[wt]) : __ldg(&c_tsdf[wt - N_GTGT]);
    out[OFF_TV + cell] = tv;
}

// scatter winner rows of current_values into zeroed current_volume
__global__ void k_scat_cur(const int* __restrict__ cc,
                           const float4* __restrict__ vals,
                           float4* __restrict__ out_cv)
{
    int tid = blockIdx.x * blockDim.x + threadIdx.x;
    if (tid >= N_CUR * NC4) return;
    int i = tid / NC4;
    int q = tid - i * NC4;
    int x = cc[3 * i + 0];
    int y = cc[3 * i + 1];
    int z = cc[3 * i + 2];
    int cell = (x * DIMV + y) * DIMV + z;
    if (g_cur_win[cell] == i)
        out_cv[cell * NC4 + q] = __ldg(&vals[tid]);
}

// scatter winner rows of global_value into zeroed global_volume
__global__ void k_scat_glb(const int* __restrict__ gc,
                           const int* __restrict__ org,
                           const float4* __restrict__ vals,
                           float4* __restrict__ out_gv)
{
    int tid = blockIdx.x * blockDim.x + threadIdx.x;
    if (tid >= N_GLB * NC4) return;
    int i = tid / NC4;
    int q = tid - i * NC4;
    int ox = __ldg(&org[0]), oy = __ldg(&org[1]), oz = __ldg(&org[2]);
    int x = gc[3 * i + 0] - ox;
    int y = gc[3 * i + 1] - oy;
    int z = gc[3 * i + 2] - oz;
    if (((unsigned)x >= DIMV) || ((unsigned)y >= DIMV) || ((unsigned)z >= DIMV)) return;
    int cell = (x * DIMV + y) * DIMV + z;
    if (g_glb_win[cell] == i)
        out_gv[cell * NC4 + q] = __ldg(&vals[tid]);
}

// ---------------------------------------------------------------------------
extern "C" void kernel_launch(void* const* d_in, const int* in_sizes, int n_in,
                              void* d_out, int out_size)
{
    const int*   current_coords     = (const int*)  d_in[0];
    const float* current_values     = (const float*)d_in[1];
    const int*   global_coords      = (const int*)  d_in[2];
    const float* global_value       = (const float*)d_in[3];
    const int*   coords_tgt_global  = (const int*)  d_in[4];
    const float* tsdf_target        = (const float*)d_in[5];
    const int*   global_coords_tgt  = (const int*)  d_in[6];
    const float* global_tsdf_target = (const float*)d_in[7];
    const int*   relative_origin    = (const int*)  d_in[8];
    const int*   grid_mask          = (const int*)  d_in[9];
    const int*   occupancy          = (const int*)  d_in[10];

    float* out = (float*)d_out;

    // Fixed, pre-existing streams only (no creation): legacy 0 + per-thread.
    cudaStream_t sB = cudaStreamPerThread;

    // Events: created once, reused deterministically every call.
    static cudaEvent_t eRoot, eCur, eGlb, eS1;
    static bool einit = false;
    if (!einit) {
        cudaEventCreateWithFlags(&eRoot, cudaEventDisableTiming);
        cudaEventCreateWithFlags(&eCur,  cudaEventDisableTiming);
        cudaEventCreateWithFlags(&eGlb,  cudaEventDisableTiming);
        cudaEventCreateWithFlags(&eS1,   cudaEventDisableTiming);
        einit = true;
    }

    const int B = 256;

    // ---- fork: sB branches off stream 0 ----
    cudaEventRecord(eRoot, 0);
    cudaStreamWaitEvent(sB, eRoot, 0);

    // ---- branch B (sB): winner-index chain (small, ~30MB traffic) ----
    k_init<<<(NCELLS + B - 1) / B, B, 0, sB>>>();
    k_cur<<<(N_CUR + B - 1) / B, B, 0, sB>>>(current_coords, grid_mask, occupancy);
    cudaEventRecord(eCur, sB);
    k_tgt<<<(N_GTGT + N_TGT + B - 1) / B, B, 0, sB>>>(global_coords_tgt,
                                                      coords_tgt_global,
                                                      relative_origin, out + OFF_VT);
    k_glb<<<(N_GLB + B - 1) / B, B, 0, sB>>>(global_coords, relative_origin,
                                             out + OFF_VAL, out + OFF_NR);
    cudaEventRecord(eGlb, sB);
    k_upd_tv<<<(NCELLS + B - 1) / B, B, 0, sB>>>(global_tsdf_target, tsdf_target, out);
    cudaEventRecord(eS1, sB);

    // ---- branch A (stream 0): bulk zero-fill (starts at t=0), then scatters ----
    cudaMemsetAsync(out + OFF_CV, 0, VOL_BYTES, 0);
    cudaMemsetAsync(out + OFF_GV, 0, VOL_BYTES, 0);
    cudaStreamWaitEvent(0, eCur, 0);
    k_scat_cur<<<(N_CUR * NC4 + B - 1) / B, B>>>(current_coords,
                                                 (const float4*)current_values,
                                                 (float4*)(out + OFF_CV));
    cudaStreamWaitEvent(0, eGlb, 0);
    k_scat_glb<<<(N_GLB * NC4 + B - 1) / B, B>>>(global_coords, relative_origin,
                                                 (const float4*)global_value,
                                                 (float4*)(out + OFF_GV));

    // ---- join: stream 0 waits for branch B ----
    cudaStreamWaitEvent(0, eS1, 0);
}